// round 2
// baseline (speedup 1.0000x reference)
#include <cuda_runtime.h>
#include <math.h>

#define SEQ 2048
#define HDIM 4096
#define NH 32
#define NKV 8
#define HD 128
#define GROUPS 4
#define KVDIM (NKV*HD)   // 1024

// ---------------- scratch (static device memory; no runtime allocation) ----
__device__ float g_xq[SEQ*HDIM];
__device__ float g_wq[HDIM*HDIM];
__device__ float g_wk[KVDIM*HDIM];
__device__ float g_wv[KVDIM*HDIM];
__device__ float g_wo[HDIM*HDIM];
__device__ float g_q[SEQ*NH*HD];
__device__ float g_k[SEQ*KVDIM];
__device__ float g_v[SEQ*KVDIM];
__device__ float g_attn[SEQ*HDIM];
__device__ float g_attnq[SEQ*HDIM];

// ---------------- row-wise fake quant (forward of STE) ---------------------
// y = clip(round(x/s), -128, 127) * s,  s = max(|x|)/127 clamped to 1e-8
__global__ void rowquant_kernel(const float* __restrict__ in,
                                float* __restrict__ out, int L) {
    int row = blockIdx.x;
    const float* x = in + (size_t)row * L;
    float* y = out + (size_t)row * L;
    __shared__ float red[256];
    float m = 0.f;
    for (int i = threadIdx.x; i < L; i += 256) m = fmaxf(m, fabsf(x[i]));
    red[threadIdx.x] = m;
    __syncthreads();
    for (int s = 128; s > 0; s >>= 1) {
        if (threadIdx.x < s) red[threadIdx.x] = fmaxf(red[threadIdx.x], red[threadIdx.x + s]);
        __syncthreads();
    }
    float scale = fmaxf(red[0] / 127.0f, 1e-8f);
    for (int i = threadIdx.x; i < L; i += 256) {
        float q = rintf(x[i] / scale);            // IEEE div + rint matches jnp.round(x/s)
        q = fminf(fmaxf(q, -128.f), 127.f);
        y[i] = q * scale;
    }
}

// ---------------- SGEMM: C[M,N] = A[M,K] @ B[N,K]^T -----------------------
// 64x64 tile, K-chunk 16, 256 threads, 4x4 microtile, float4 tile fills.
#define TM 64
#define TN 64
#define TKC 16
__global__ void gemm_abt_kernel(const float* __restrict__ A,
                                const float* __restrict__ B,
                                float* __restrict__ C,
                                int M, int N, int K) {
    __shared__ float As[TKC][TM + 1];
    __shared__ float Bs[TKC][TN + 1];
    int tx = threadIdx.x & 15, ty = threadIdx.x >> 4;   // 16x16 threads
    int m0 = blockIdx.y * TM, n0 = blockIdx.x * TN;
    // each thread loads one float4 of A-tile and one of B-tile per K-chunk
    int lr = threadIdx.x >> 2;            // row in tile 0..63
    int lc = (threadIdx.x & 3) * 4;       // k offset 0,4,8,12
    float acc[4][4] = {};
    for (int k0 = 0; k0 < K; k0 += TKC) {
        float4 av = *(const float4*)(A + (size_t)(m0 + lr) * K + k0 + lc);
        float4 bv = *(const float4*)(B + (size_t)(n0 + lr) * K + k0 + lc);
        As[lc + 0][lr] = av.x; As[lc + 1][lr] = av.y;
        As[lc + 2][lr] = av.z; As[lc + 3][lr] = av.w;
        Bs[lc + 0][lr] = bv.x; Bs[lc + 1][lr] = bv.y;
        Bs[lc + 2][lr] = bv.z; Bs[lc + 3][lr] = bv.w;
        __syncthreads();
        #pragma unroll
        for (int kk = 0; kk < TKC; kk++) {
            float a[4], b[4];
            #pragma unroll
            for (int i = 0; i < 4; i++) a[i] = As[kk][ty * 4 + i];
            #pragma unroll
            for (int j = 0; j < 4; j++) b[j] = Bs[kk][tx * 4 + j];
            #pragma unroll
            for (int i = 0; i < 4; i++)
                #pragma unroll
                for (int j = 0; j < 4; j++) acc[i][j] += a[i] * b[j];
        }
        __syncthreads();
    }
    #pragma unroll
    for (int i = 0; i < 4; i++) {
        float4 cv = make_float4(acc[i][0], acc[i][1], acc[i][2], acc[i][3]);
        *(float4*)(C + (size_t)(m0 + ty * 4 + i) * N + n0 + tx * 4) = cv;
    }
}

// ---------------- RoPE (in-place), layout [S, nheads*HD] -------------------
__global__ void rope_kernel(float* __restrict__ q, const float* __restrict__ cosb,
                            const float* __restrict__ sinb, int nheads) {
    int s = blockIdx.x;
    int h = blockIdx.y;
    int d = threadIdx.x;   // 0..63
    float* row = q + (size_t)s * nheads * HD + h * HD;
    float c1 = cosb[s * HD + d],      s1 = sinb[s * HD + d];
    float c2 = cosb[s * HD + d + 64], s2 = sinb[s * HD + d + 64];
    float x1 = row[d], x2 = row[d + 64];
    row[d]      = x1 * c1 - x2 * s1;
    row[d + 64] = x2 * c2 + x1 * s2;
}

// ---------------- causal GQA flash attention -------------------------------
// grid: (S/64, NH), 128 threads. Q tile 64, K tile 64, online softmax.
#define KSS 129   // padded row stride for K/V tiles
#define SSS 65    // padded row stride for score tile
__global__ void attn_kernel(const float* __restrict__ Q, const float* __restrict__ K,
                            const float* __restrict__ V, float* __restrict__ O) {
    extern __shared__ float sm[];
    float* Qs = sm;                    // 64*128
    float* Ks = Qs + 64 * 128;         // 64*KSS
    float* Vs = Ks + 64 * KSS;         // 64*KSS
    float* Ss = Vs + 64 * KSS;         // 64*SSS
    int h = blockIdx.y;
    int kvh = h / GROUPS;
    int q0 = blockIdx.x * 64;
    int t = threadIdx.x;               // 0..127
    int row = t >> 1;
    int c0 = (t & 1) * 64;

    for (int i = t; i < 64 * 128; i += 128) {
        int r = i >> 7, d = i & 127;
        Qs[i] = Q[(size_t)(q0 + r) * (NH * HD) + h * HD + d];
    }

    float acc[64];
    #pragma unroll
    for (int i = 0; i < 64; i++) acc[i] = 0.f;
    float mrow = -INFINITY, lrow = 0.f;
    const float scale = 0.08838834764831845f;  // 128^-0.5

    int kend = q0 + 64;
    for (int k0 = 0; k0 < kend; k0 += 64) {
        __syncthreads();
        for (int i = t; i < 64 * 128; i += 128) {
            int r = i >> 7, d = i & 127;
            Ks[r * KSS + d] = K[(size_t)(k0 + r) * KVDIM + kvh * HD + d];
            Vs[r * KSS + d] = V[(size_t)(k0 + r) * KVDIM + kvh * HD + d];
        }
        __syncthreads();
        // scores (32 per thread)
        for (int idx = t; idx < 64 * 64; idx += 128) {
            int i = idx >> 6, j = idx & 63;
            float sd;
            if (k0 + j <= q0 + i) {
                const float* qp = Qs + i * 128;
                const float* kp = Ks + j * KSS;
                sd = 0.f;
                #pragma unroll 16
                for (int d = 0; d < 128; d++) sd += qp[d] * kp[d];
                sd *= scale;
            } else sd = -INFINITY;
            Ss[i * SSS + j] = sd;
        }
        __syncthreads();
        // online softmax for this thread's row
        float mnew = mrow;
        for (int j = 0; j < 64; j++) mnew = fmaxf(mnew, Ss[row * SSS + j]);
        float alpha = expf(mrow - mnew);
        if ((t & 1) == 0) {
            for (int j = 0; j < 64; j++)
                Ss[row * SSS + j] = expf(Ss[row * SSS + j] - mnew);
        }
        __syncthreads();
        float lsum = 0.f;
        for (int j = 0; j < 64; j++) lsum = lsum + Ss[row * SSS + j];
        #pragma unroll
        for (int c = 0; c < 64; c++) acc[c] *= alpha;
        for (int j = 0; j < 64; j++) {
            float p = Ss[row * SSS + j];
            const float* vp = Vs + j * KSS + c0;
            #pragma unroll 16
            for (int c = 0; c < 64; c++) acc[c] += p * vp[c];
        }
        lrow = lrow * alpha + lsum;
        mrow = mnew;
    }
    float inv_l = 1.f / lrow;
    float* op = O + (size_t)(q0 + row) * HDIM + h * HD + c0;
    #pragma unroll
    for (int c = 0; c < 64; c++) op[c] = acc[c] * inv_l;
}

// ---------------- launch ---------------------------------------------------
extern "C" void kernel_launch(void* const* d_in, const int* in_sizes, int n_in,
                              void* d_out, int out_size) {
    const float* hidden = (const float*)d_in[0];
    const float* cosb   = (const float*)d_in[1];
    const float* sinb   = (const float*)d_in[2];
    const float* Wq     = (const float*)d_in[3];
    const float* Wk     = (const float*)d_in[4];
    const float* Wv     = (const float*)d_in[5];
    const float* Wo     = (const float*)d_in[6];
    float* out = (float*)d_out;

    void *p_xq, *p_wq, *p_wk, *p_wv, *p_wo, *p_q, *p_k, *p_v, *p_attn, *p_attnq;
    cudaGetSymbolAddress(&p_xq, g_xq);
    cudaGetSymbolAddress(&p_wq, g_wq);
    cudaGetSymbolAddress(&p_wk, g_wk);
    cudaGetSymbolAddress(&p_wv, g_wv);
    cudaGetSymbolAddress(&p_wo, g_wo);
    cudaGetSymbolAddress(&p_q, g_q);
    cudaGetSymbolAddress(&p_k, g_k);
    cudaGetSymbolAddress(&p_v, g_v);
    cudaGetSymbolAddress(&p_attn, g_attn);
    cudaGetSymbolAddress(&p_attnq, g_attnq);
    float* xq = (float*)p_xq;  float* wq = (float*)p_wq;  float* wk = (float*)p_wk;
    float* wv = (float*)p_wv;  float* wo = (float*)p_wo;  float* q  = (float*)p_q;
    float* k  = (float*)p_k;   float* v  = (float*)p_v;
    float* attn = (float*)p_attn; float* attnq = (float*)p_attnq;

    // 1. quantize activations + weights
    rowquant_kernel<<<SEQ, 256>>>(hidden, xq, HDIM);
    rowquant_kernel<<<HDIM, 256>>>(Wq, wq, HDIM);
    rowquant_kernel<<<KVDIM, 256>>>(Wk, wk, HDIM);
    rowquant_kernel<<<KVDIM, 256>>>(Wv, wv, HDIM);
    rowquant_kernel<<<HDIM, 256>>>(Wo, wo, HDIM);

    // 2. projections
    gemm_abt_kernel<<<dim3(HDIM / TN, SEQ / TM), 256>>>(xq, wq, q, SEQ, HDIM, HDIM);
    gemm_abt_kernel<<<dim3(KVDIM / TN, SEQ / TM), 256>>>(xq, wk, k, SEQ, KVDIM, HDIM);
    gemm_abt_kernel<<<dim3(KVDIM / TN, SEQ / TM), 256>>>(xq, wv, v, SEQ, KVDIM, HDIM);

    // 3. RoPE
    rope_kernel<<<dim3(SEQ, NH), 64>>>(q, cosb, sinb, NH);
    rope_kernel<<<dim3(SEQ, NKV), 64>>>(k, cosb, sinb, NKV);

    // 4. attention
    size_t smem = (size_t)(64 * 128 + 2 * 64 * KSS + 64 * SSS) * sizeof(float);
    cudaFuncSetAttribute(attn_kernel, cudaFuncAttributeMaxDynamicSharedMemorySize, (int)smem);
    attn_kernel<<<dim3(SEQ / 64, NH), 128, smem>>>(q, k, v, attn);

    // 5. output quant + projection
    rowquant_kernel<<<SEQ, 256>>>(attn, attnq, HDIM);
    gemm_abt_kernel<<<dim3(HDIM / TN, SEQ / TM), 256>>>(attnq, wo, out, SEQ, HDIM, HDIM);
}

// round 4
// speedup vs baseline: 1.6177x; 1.6177x over previous
#include <cuda_runtime.h>
#include <math.h>
#include <stdint.h>

#define SEQ 2048
#define HDIM 4096
#define NH 32
#define NKV 8
#define HD 128
#define GROUPS 4
#define KVDIM (NKV*HD)   // 1024

// ---------------- scratch (static device memory) ---------------------------
__device__ int8_t i8_x[SEQ*HDIM];     __device__ float s_x[SEQ];
__device__ int8_t i8_wq[HDIM*HDIM];   __device__ float s_wq[HDIM];
__device__ int8_t i8_wk[KVDIM*HDIM];  __device__ float s_wk[KVDIM];
__device__ int8_t i8_wv[KVDIM*HDIM];  __device__ float s_wv[KVDIM];
__device__ int8_t i8_wo[HDIM*HDIM];   __device__ float s_wo[HDIM];
__device__ int8_t i8_attn[SEQ*HDIM];  __device__ float s_attn[SEQ];
__device__ float g_q[SEQ*NH*HD];
__device__ float g_k[SEQ*KVDIM];
__device__ float g_v[SEQ*KVDIM];
__device__ float g_attn[SEQ*HDIM];

// ---------------- row-wise fake quant -> int8 + scale ----------------------
// n = clip(round(x/s), -128, 127),  s = max(|x|)/127 clamped to 1e-8
__global__ void rowquant_kernel(const float* __restrict__ in,
                                int8_t* __restrict__ out8,
                                float* __restrict__ scales, int L) {
    int row = blockIdx.x;
    const float* x = in + (size_t)row * L;
    int8_t* y = out8 + (size_t)row * L;
    __shared__ float red[256];
    float m = 0.f;
    for (int i = threadIdx.x; i < L; i += 256) m = fmaxf(m, fabsf(x[i]));
    red[threadIdx.x] = m;
    __syncthreads();
    for (int s = 128; s > 0; s >>= 1) {
        if (threadIdx.x < s) red[threadIdx.x] = fmaxf(red[threadIdx.x], red[threadIdx.x + s]);
        __syncthreads();
    }
    float scale = fmaxf(__fdiv_rn(red[0], 127.0f), 1e-8f);
    if (threadIdx.x == 0) scales[row] = scale;
    for (int i = threadIdx.x; i < L; i += 256) {
        float q = rintf(__fdiv_rn(x[i], scale));   // IEEE div, ties-to-even
        q = fminf(fmaxf(q, -128.f), 127.f);
        y[i] = (int8_t)(int)q;
    }
}

// ---------------- int8 IMMA GEMM: C[M,N] = sa[m]*sb[n]*(A8[m,:] . B8[n,:]) --
// 128x128 block tile, BK=64, 256 threads (8 warps 2x4), warp tile 64x32.
#define BM 128
#define BN 128
#define BKQ 64
#define ASTRB 80          // padded byte stride of smem tile rows
__global__ void __launch_bounds__(256, 2)
gemm_s8_kernel(const int8_t* __restrict__ A, const int8_t* __restrict__ B,
               const float* __restrict__ sa, const float* __restrict__ sb,
               float* __restrict__ C, int M, int N, int K) {
    __shared__ uint8_t As[BM * ASTRB];
    __shared__ uint8_t Bs[BN * ASTRB];
    int tid = threadIdx.x;
    int warp = tid >> 5, lane = tid & 31;
    int gid = lane >> 2, tig = lane & 3;
    int wm0 = (warp & 1) * 64;
    int wn0 = (warp >> 1) * 32;
    int m0 = blockIdx.y * BM, n0 = blockIdx.x * BN;

    int lrow = tid >> 2;            // 0..63 (two passes cover 128 rows)
    int lcol = (tid & 3) * 16;      // 0,16,32,48

    int acc[4][4][4];
    #pragma unroll
    for (int i = 0; i < 4; i++)
        #pragma unroll
        for (int j = 0; j < 4; j++)
            #pragma unroll
            for (int c = 0; c < 4; c++) acc[i][j][c] = 0;

    const uint32_t* As32 = (const uint32_t*)As;
    const uint32_t* Bs32 = (const uint32_t*)Bs;

    for (int k0 = 0; k0 < K; k0 += BKQ) {
        #pragma unroll
        for (int p = 0; p < 2; p++) {
            int r = lrow + p * 64;
            *(int4*)(As + r * ASTRB + lcol) =
                *(const int4*)(A + (size_t)(m0 + r) * K + k0 + lcol);
            *(int4*)(Bs + r * ASTRB + lcol) =
                *(const int4*)(B + (size_t)(n0 + r) * K + k0 + lcol);
        }
        __syncthreads();
        #pragma unroll
        for (int ks = 0; ks < 2; ks++) {
            int kb = ks * 8;   // in 32-bit words (32 bytes)
            uint32_t a[4][4], b[4][2];
            #pragma unroll
            for (int mi = 0; mi < 4; mi++) {
                int r1 = wm0 + mi * 16 + gid;
                a[mi][0] = As32[r1 * 20 + kb + tig];
                a[mi][1] = As32[(r1 + 8) * 20 + kb + tig];
                a[mi][2] = As32[r1 * 20 + kb + tig + 4];
                a[mi][3] = As32[(r1 + 8) * 20 + kb + tig + 4];
            }
            #pragma unroll
            for (int ni = 0; ni < 4; ni++) {
                int rb = wn0 + ni * 8 + gid;
                b[ni][0] = Bs32[rb * 20 + kb + tig];
                b[ni][1] = Bs32[rb * 20 + kb + tig + 4];
            }
            #pragma unroll
            for (int mi = 0; mi < 4; mi++)
                #pragma unroll
                for (int ni = 0; ni < 4; ni++) {
                    asm volatile(
                        "mma.sync.aligned.m16n8k32.row.col.s32.s8.s8.s32 "
                        "{%0,%1,%2,%3}, {%4,%5,%6,%7}, {%8,%9}, {%0,%1,%2,%3};\n"
                        : "+r"(acc[mi][ni][0]), "+r"(acc[mi][ni][1]),
                          "+r"(acc[mi][ni][2]), "+r"(acc[mi][ni][3])
                        : "r"(a[mi][0]), "r"(a[mi][1]), "r"(a[mi][2]), "r"(a[mi][3]),
                          "r"(b[ni][0]), "r"(b[ni][1]));
                }
        }
        __syncthreads();
    }
    // epilogue: scale and store
    #pragma unroll
    for (int mi = 0; mi < 4; mi++) {
        int r0 = m0 + wm0 + mi * 16 + gid;
        float sa0 = sa[r0], sa1 = sa[r0 + 8];
        #pragma unroll
        for (int ni = 0; ni < 4; ni++) {
            int c = n0 + wn0 + ni * 8 + tig * 2;
            float sb0 = sb[c], sb1 = sb[c + 1];
            *(float2*)(C + (size_t)r0 * N + c) = make_float2(
                __fmul_rn(__fmul_rn((float)acc[mi][ni][0], sa0), sb0),
                __fmul_rn(__fmul_rn((float)acc[mi][ni][1], sa0), sb1));
            *(float2*)(C + (size_t)(r0 + 8) * N + c) = make_float2(
                __fmul_rn(__fmul_rn((float)acc[mi][ni][2], sa1), sb0),
                __fmul_rn(__fmul_rn((float)acc[mi][ni][3], sa1), sb1));
        }
    }
}

// ---------------- RoPE (in-place), layout [S, nheads*HD] -------------------
__global__ void rope_kernel(float* __restrict__ q, const float* __restrict__ cosb,
                            const float* __restrict__ sinb, int nheads) {
    int s = blockIdx.x;
    int h = blockIdx.y;
    int d = threadIdx.x;   // 0..63
    float* row = q + (size_t)s * nheads * HD + h * HD;
    float c1 = cosb[s * HD + d],      s1 = sinb[s * HD + d];
    float c2 = cosb[s * HD + d + 64], s2 = sinb[s * HD + d + 64];
    float x1 = row[d], x2 = row[d + 64];
    row[d]      = __fsub_rn(__fmul_rn(x1, c1), __fmul_rn(x2, s1));
    row[d + 64] = __fadd_rn(__fmul_rn(x2, c2), __fmul_rn(x1, s2));
}

// ---------------- causal GQA flash attention (R2 version, fp32) ------------
#define KSS 129
#define SSS 65
__global__ void attn_kernel(const float* __restrict__ Q, const float* __restrict__ K,
                            const float* __restrict__ V, float* __restrict__ O) {
    extern __shared__ float sm[];
    float* Qs = sm;                    // 64*128
    float* Ks = Qs + 64 * 128;         // 64*KSS
    float* Vs = Ks + 64 * KSS;         // 64*KSS
    float* Ss = Vs + 64 * KSS;         // 64*SSS
    int h = blockIdx.y;
    int kvh = h / GROUPS;
    int q0 = blockIdx.x * 64;
    int t = threadIdx.x;               // 0..127
    int row = t >> 1;
    int c0 = (t & 1) * 64;

    for (int i = t; i < 64 * 128; i += 128) {
        int r = i >> 7, d = i & 127;
        Qs[i] = Q[(size_t)(q0 + r) * (NH * HD) + h * HD + d];
    }

    float acc[64];
    #pragma unroll
    for (int i = 0; i < 64; i++) acc[i] = 0.f;
    float mrow = -INFINITY, lrow = 0.f;
    const float scale = 0.08838834764831845f;  // 128^-0.5

    int kend = q0 + 64;
    for (int k0 = 0; k0 < kend; k0 += 64) {
        __syncthreads();
        for (int i = t; i < 64 * 128; i += 128) {
            int r = i >> 7, d = i & 127;
            Ks[r * KSS + d] = K[(size_t)(k0 + r) * KVDIM + kvh * HD + d];
            Vs[r * KSS + d] = V[(size_t)(k0 + r) * KVDIM + kvh * HD + d];
        }
        __syncthreads();
        for (int idx = t; idx < 64 * 64; idx += 128) {
            int i = idx >> 6, j = idx & 63;
            float sd;
            if (k0 + j <= q0 + i) {
                const float* qp = Qs + i * 128;
                const float* kp = Ks + j * KSS;
                sd = 0.f;
                #pragma unroll 16
                for (int d = 0; d < 128; d++) sd += qp[d] * kp[d];
                sd = __fmul_rn(sd, scale);
            } else sd = -INFINITY;
            Ss[i * SSS + j] = sd;
        }
        __syncthreads();
        float mnew = mrow;
        for (int j = 0; j < 64; j++) mnew = fmaxf(mnew, Ss[row * SSS + j]);
        float alpha = expf(mrow - mnew);
        if ((t & 1) == 0) {
            for (int j = 0; j < 64; j++)
                Ss[row * SSS + j] = expf(Ss[row * SSS + j] - mnew);
        }
        __syncthreads();
        float lsum = 0.f;
        for (int j = 0; j < 64; j++) lsum = lsum + Ss[row * SSS + j];
        #pragma unroll
        for (int c = 0; c < 64; c++) acc[c] *= alpha;
        for (int j = 0; j < 64; j++) {
            float p = Ss[row * SSS + j];
            const float* vp = Vs + j * KSS + c0;
            #pragma unroll 16
            for (int c = 0; c < 64; c++) acc[c] += p * vp[c];
        }
        lrow = lrow * alpha + lsum;
        mrow = mnew;
    }
    float inv_l = __fdiv_rn(1.f, lrow);
    float* op = O + (size_t)(q0 + row) * HDIM + h * HD + c0;
    #pragma unroll
    for (int c = 0; c < 64; c++) op[c] = __fmul_rn(acc[c], inv_l);
}

// ---------------- launch ---------------------------------------------------
extern "C" void kernel_launch(void* const* d_in, const int* in_sizes, int n_in,
                              void* d_out, int out_size) {
    const float* hidden = (const float*)d_in[0];
    const float* cosb   = (const float*)d_in[1];
    const float* sinb   = (const float*)d_in[2];
    const float* Wq     = (const float*)d_in[3];
    const float* Wk     = (const float*)d_in[4];
    const float* Wv     = (const float*)d_in[5];
    const float* Wo     = (const float*)d_in[6];
    float* out = (float*)d_out;

    void *px, *psx, *pwq, *pswq, *pwk, *pswk, *pwv, *pswv, *pwo, *pswo;
    void *pq, *pk, *pv, *pattn, *pattn8, *psattn;
    cudaGetSymbolAddress(&px, i8_x);      cudaGetSymbolAddress(&psx, s_x);
    cudaGetSymbolAddress(&pwq, i8_wq);    cudaGetSymbolAddress(&pswq, s_wq);
    cudaGetSymbolAddress(&pwk, i8_wk);    cudaGetSymbolAddress(&pswk, s_wk);
    cudaGetSymbolAddress(&pwv, i8_wv);    cudaGetSymbolAddress(&pswv, s_wv);
    cudaGetSymbolAddress(&pwo, i8_wo);    cudaGetSymbolAddress(&pswo, s_wo);
    cudaGetSymbolAddress(&pq, g_q);       cudaGetSymbolAddress(&pk, g_k);
    cudaGetSymbolAddress(&pv, g_v);       cudaGetSymbolAddress(&pattn, g_attn);
    cudaGetSymbolAddress(&pattn8, i8_attn); cudaGetSymbolAddress(&psattn, s_attn);

    int8_t* x8 = (int8_t*)px;    float* sx = (float*)psx;
    int8_t* wq8 = (int8_t*)pwq;  float* swq = (float*)pswq;
    int8_t* wk8 = (int8_t*)pwk;  float* swk = (float*)pswk;
    int8_t* wv8 = (int8_t*)pwv;  float* swv = (float*)pswv;
    int8_t* wo8 = (int8_t*)pwo;  float* swo = (float*)pswo;
    float* q = (float*)pq;  float* k = (float*)pk;  float* v = (float*)pv;
    float* attn = (float*)pattn;
    int8_t* attn8 = (int8_t*)pattn8; float* sattn = (float*)psattn;

    // 1. fake-quant -> int8 + scales
    rowquant_kernel<<<SEQ, 256>>>(hidden, x8, sx, HDIM);
    rowquant_kernel<<<HDIM, 256>>>(Wq, wq8, swq, HDIM);
    rowquant_kernel<<<KVDIM, 256>>>(Wk, wk8, swk, HDIM);
    rowquant_kernel<<<KVDIM, 256>>>(Wv, wv8, swv, HDIM);
    rowquant_kernel<<<HDIM, 256>>>(Wo, wo8, swo, HDIM);

    // 2. projections (exact int8 tensor cores + fp32 scaling)
    gemm_s8_kernel<<<dim3(HDIM / BN, SEQ / BM), 256>>>(x8, wq8, sx, swq, q, SEQ, HDIM, HDIM);
    gemm_s8_kernel<<<dim3(KVDIM / BN, SEQ / BM), 256>>>(x8, wk8, sx, swk, k, SEQ, KVDIM, HDIM);
    gemm_s8_kernel<<<dim3(KVDIM / BN, SEQ / BM), 256>>>(x8, wv8, sx, swv, v, SEQ, KVDIM, HDIM);

    // 3. RoPE (fp32, in-place)
    rope_kernel<<<dim3(SEQ, NH), 64>>>(q, cosb, sinb, NH);
    rope_kernel<<<dim3(SEQ, NKV), 64>>>(k, cosb, sinb, NKV);

    // 4. attention (fp32, online softmax)
    size_t smem = (size_t)(64 * 128 + 2 * 64 * KSS + 64 * SSS) * sizeof(float);
    cudaFuncSetAttribute(attn_kernel, cudaFuncAttributeMaxDynamicSharedMemorySize, (int)smem);
    attn_kernel<<<dim3(SEQ / 64, NH), 128, smem>>>(q, k, v, attn);

    // 5. output quant + projection
    rowquant_kernel<<<SEQ, 256>>>(attn, attn8, sattn, HDIM);
    gemm_s8_kernel<<<dim3(HDIM / BN, SEQ / BM), 256>>>(attn8, wo8, sattn, swo, out, SEQ, HDIM, HDIM);
}

// round 5
// speedup vs baseline: 7.7653x; 4.8003x over previous
#include <cuda_runtime.h>
#include <math.h>
#include <stdint.h>

#define SEQ 2048
#define HDIM 4096
#define NH 32
#define NKV 8
#define HD 128
#define GROUPS 4
#define KVDIM (NKV*HD)   // 1024

// ---------------- scratch (static device memory) ---------------------------
__device__ int8_t i8_x[SEQ*HDIM];     __device__ float s_x[SEQ];
__device__ int8_t i8_wq[HDIM*HDIM];   __device__ float s_wq[HDIM];
__device__ int8_t i8_wk[KVDIM*HDIM];  __device__ float s_wk[KVDIM];
__device__ int8_t i8_wv[KVDIM*HDIM];  __device__ float s_wv[KVDIM];
__device__ int8_t i8_wo[HDIM*HDIM];   __device__ float s_wo[HDIM];
__device__ int8_t i8_attn[SEQ*HDIM];  __device__ float s_attn[SEQ];
__device__ float g_q[SEQ*NH*HD];
__device__ float g_k[SEQ*KVDIM];
__device__ float g_v[SEQ*KVDIM];
__device__ float g_attn[SEQ*HDIM];

// ---------------- packed f32x2 helpers (exact per-lane fp32 FMA) -----------
__device__ __forceinline__ unsigned long long pk2(float x, float y) {
    unsigned long long r; asm("mov.b64 %0, {%1, %2};" : "=l"(r) : "f"(x), "f"(y)); return r;
}
__device__ __forceinline__ void upk2(unsigned long long v, float& x, float& y) {
    asm("mov.b64 {%0, %1}, %2;" : "=f"(x), "=f"(y) : "l"(v));
}
__device__ __forceinline__ unsigned long long fma2_(unsigned long long a,
                                                    unsigned long long b,
                                                    unsigned long long c) {
    unsigned long long d;
    asm("fma.rn.f32x2 %0, %1, %2, %3;" : "=l"(d) : "l"(a), "l"(b), "l"(c));
    return d;
}
__device__ __forceinline__ unsigned long long mul2_(unsigned long long a,
                                                    unsigned long long b) {
    unsigned long long d;
    asm("mul.rn.f32x2 %0, %1, %2;" : "=l"(d) : "l"(a), "l"(b));
    return d;
}

// ---------------- row-wise fake quant -> int8 + scale ----------------------
__global__ void rowquant_kernel(const float* __restrict__ in,
                                int8_t* __restrict__ out8,
                                float* __restrict__ scales, int L) {
    int row = blockIdx.x;
    const float* x = in + (size_t)row * L;
    int8_t* y = out8 + (size_t)row * L;
    __shared__ float red[256];
    float m = 0.f;
    for (int i = threadIdx.x; i < L; i += 256) m = fmaxf(m, fabsf(x[i]));
    red[threadIdx.x] = m;
    __syncthreads();
    for (int s = 128; s > 0; s >>= 1) {
        if (threadIdx.x < s) red[threadIdx.x] = fmaxf(red[threadIdx.x], red[threadIdx.x + s]);
        __syncthreads();
    }
    float scale = fmaxf(__fdiv_rn(red[0], 127.0f), 1e-8f);
    if (threadIdx.x == 0) scales[row] = scale;
    for (int i = threadIdx.x; i < L; i += 256) {
        float q = rintf(__fdiv_rn(x[i], scale));
        q = fminf(fmaxf(q, -128.f), 127.f);
        y[i] = (int8_t)(int)q;
    }
}

// ---------------- int8 IMMA GEMM (unchanged from R4) -----------------------
#define BM 128
#define BN 128
#define BKQ 64
#define ASTRB 80
__global__ void __launch_bounds__(256, 2)
gemm_s8_kernel(const int8_t* __restrict__ A, const int8_t* __restrict__ B,
               const float* __restrict__ sa, const float* __restrict__ sb,
               float* __restrict__ C, int M, int N, int K) {
    __shared__ uint8_t As[BM * ASTRB];
    __shared__ uint8_t Bs[BN * ASTRB];
    int tid = threadIdx.x;
    int warp = tid >> 5, lane = tid & 31;
    int gid = lane >> 2, tig = lane & 3;
    int wm0 = (warp & 1) * 64;
    int wn0 = (warp >> 1) * 32;
    int m0 = blockIdx.y * BM, n0 = blockIdx.x * BN;

    int lrow = tid >> 2;
    int lcol = (tid & 3) * 16;

    int acc[4][4][4];
    #pragma unroll
    for (int i = 0; i < 4; i++)
        #pragma unroll
        for (int j = 0; j < 4; j++)
            #pragma unroll
            for (int c = 0; c < 4; c++) acc[i][j][c] = 0;

    const uint32_t* As32 = (const uint32_t*)As;
    const uint32_t* Bs32 = (const uint32_t*)Bs;

    for (int k0 = 0; k0 < K; k0 += BKQ) {
        #pragma unroll
        for (int p = 0; p < 2; p++) {
            int r = lrow + p * 64;
            *(int4*)(As + r * ASTRB + lcol) =
                *(const int4*)(A + (size_t)(m0 + r) * K + k0 + lcol);
            *(int4*)(Bs + r * ASTRB + lcol) =
                *(const int4*)(B + (size_t)(n0 + r) * K + k0 + lcol);
        }
        __syncthreads();
        #pragma unroll
        for (int ks = 0; ks < 2; ks++) {
            int kb = ks * 8;
            uint32_t a[4][4], b[4][2];
            #pragma unroll
            for (int mi = 0; mi < 4; mi++) {
                int r1 = wm0 + mi * 16 + gid;
                a[mi][0] = As32[r1 * 20 + kb + tig];
                a[mi][1] = As32[(r1 + 8) * 20 + kb + tig];
                a[mi][2] = As32[r1 * 20 + kb + tig + 4];
                a[mi][3] = As32[(r1 + 8) * 20 + kb + tig + 4];
            }
            #pragma unroll
            for (int ni = 0; ni < 4; ni++) {
                int rb = wn0 + ni * 8 + gid;
                b[ni][0] = Bs32[rb * 20 + kb + tig];
                b[ni][1] = Bs32[rb * 20 + kb + tig + 4];
            }
            #pragma unroll
            for (int mi = 0; mi < 4; mi++)
                #pragma unroll
                for (int ni = 0; ni < 4; ni++) {
                    asm volatile(
                        "mma.sync.aligned.m16n8k32.row.col.s32.s8.s8.s32 "
                        "{%0,%1,%2,%3}, {%4,%5,%6,%7}, {%8,%9}, {%0,%1,%2,%3};\n"
                        : "+r"(acc[mi][ni][0]), "+r"(acc[mi][ni][1]),
                          "+r"(acc[mi][ni][2]), "+r"(acc[mi][ni][3])
                        : "r"(a[mi][0]), "r"(a[mi][1]), "r"(a[mi][2]), "r"(a[mi][3]),
                          "r"(b[ni][0]), "r"(b[ni][1]));
                }
        }
        __syncthreads();
    }
    #pragma unroll
    for (int mi = 0; mi < 4; mi++) {
        int r0 = m0 + wm0 + mi * 16 + gid;
        float sa0 = sa[r0], sa1 = sa[r0 + 8];
        #pragma unroll
        for (int ni = 0; ni < 4; ni++) {
            int c = n0 + wn0 + ni * 8 + tig * 2;
            float sb0 = sb[c], sb1 = sb[c + 1];
            *(float2*)(C + (size_t)r0 * N + c) = make_float2(
                __fmul_rn(__fmul_rn((float)acc[mi][ni][0], sa0), sb0),
                __fmul_rn(__fmul_rn((float)acc[mi][ni][1], sa0), sb1));
            *(float2*)(C + (size_t)(r0 + 8) * N + c) = make_float2(
                __fmul_rn(__fmul_rn((float)acc[mi][ni][2], sa1), sb0),
                __fmul_rn(__fmul_rn((float)acc[mi][ni][3], sa1), sb1));
        }
    }
}

// ---------------- RoPE (in-place) ------------------------------------------
__global__ void rope_kernel(float* __restrict__ q, const float* __restrict__ cosb,
                            const float* __restrict__ sinb, int nheads) {
    int s = blockIdx.x;
    int h = blockIdx.y;
    int d = threadIdx.x;
    float* row = q + (size_t)s * nheads * HD + h * HD;
    float c1 = cosb[s * HD + d],      s1 = sinb[s * HD + d];
    float c2 = cosb[s * HD + d + 64], s2 = sinb[s * HD + d + 64];
    float x1 = row[d], x2 = row[d + 64];
    row[d]      = __fsub_rn(__fmul_rn(x1, c1), __fmul_rn(x2, s1));
    row[d + 64] = __fadd_rn(__fmul_rn(x2, c2), __fmul_rn(x1, s2));
}

// ---------------- causal GQA flash attention, 128x128 tiles, f32x2 ---------
// smem tiles: 128 rows x 128 floats (512B/row), XOR-swizzled at 16B grain.
#define SWZ(row, c4) (((row) << 9) + (((c4) << 4) ^ ((((row) >> 3) & 7) << 4)))
#define ATTN_SMEM (3 * 128 * 512)

__global__ void __launch_bounds__(256, 1)
attn_kernel(const float* __restrict__ Q, const float* __restrict__ K,
            const float* __restrict__ V, float* __restrict__ O) {
    extern __shared__ char smem[];
    char* qs = smem;                 // Q tile  [128][128]f
    char* ks = smem + 65536;         // K tile, reused for V
    char* ps = smem + 131072;        // P tile  [128][128]f
    int h = blockIdx.y;
    int kvh = h / GROUPS;
    int qi = (int)gridDim.x - 1 - (int)blockIdx.x;   // heavy tiles first
    int q0 = qi * 128;
    int t = threadIdx.x;
    int lane5 = t & 31, warp = t >> 5;
    int tx = t & 15, ty = t >> 4;
    const float scale = 0.08838834764831845f;

    // load Q tile (coalesced, swizzled store)
    #pragma unroll 4
    for (int p = 0; p < 16; p++) {
        int r = p * 8 + warp;
        float4 v = *(const float4*)(Q + (size_t)(q0 + r) * (NH * HD) + h * HD + lane5 * 4);
        *(float4*)(qs + SWZ(r, lane5)) = v;
    }

    unsigned long long oacc[8][4];
    float mrun[8], lrun[8];
    #pragma unroll
    for (int i = 0; i < 8; i++) {
        mrun[i] = -INFINITY; lrun[i] = 0.f;
        #pragma unroll
        for (int jp = 0; jp < 4; jp++) oacc[i][jp] = 0ull;
    }

    for (int kt = 0; kt <= qi; kt++) {
        int k0 = kt * 128;
        __syncthreads();   // prior PV reads of ks done
        #pragma unroll 4
        for (int p = 0; p < 16; p++) {
            int r = p * 8 + warp;
            float4 v = *(const float4*)(K + (size_t)(k0 + r) * KVDIM + kvh * HD + lane5 * 4);
            *(float4*)(ks + SWZ(r, lane5)) = v;
        }
        __syncthreads();

        // ---- scores: S[ty*8+i][tx*8+j], d-order 0..127 per element ----
        unsigned long long sacc[8][4];
        #pragma unroll
        for (int i = 0; i < 8; i++)
            #pragma unroll
            for (int jp = 0; jp < 4; jp++) sacc[i][jp] = 0ull;

        for (int dc = 0; dc < 32; dc++) {
            float4 qv[8], kv[8];
            #pragma unroll
            for (int i = 0; i < 8; i++) qv[i] = *(const float4*)(qs + SWZ(ty * 8 + i, dc));
            #pragma unroll
            for (int j = 0; j < 8; j++) kv[j] = *(const float4*)(ks + SWZ(tx * 8 + j, dc));
            #pragma unroll
            for (int c = 0; c < 4; c++) {
                unsigned long long b2[4];
                #pragma unroll
                for (int jp = 0; jp < 4; jp++) {
                    float b0 = ((const float*)&kv[2 * jp])[c];
                    float b1 = ((const float*)&kv[2 * jp + 1])[c];
                    b2[jp] = pk2(b0, b1);
                }
                #pragma unroll
                for (int i = 0; i < 8; i++) {
                    float av = ((const float*)&qv[i])[c];
                    unsigned long long a2 = pk2(av, av);
                    #pragma unroll
                    for (int jp = 0; jp < 4; jp++)
                        sacc[i][jp] = fma2_(a2, b2[jp], sacc[i][jp]);
                }
            }
        }

        // ---- softmax (registers + width-16 shfl) ----
        bool diag = (kt == qi);
        #pragma unroll
        for (int i = 0; i < 8; i++) {
            float s[8];
            #pragma unroll
            for (int jp = 0; jp < 4; jp++) upk2(sacc[i][jp], s[2 * jp], s[2 * jp + 1]);
            #pragma unroll
            for (int j = 0; j < 8; j++) {
                s[j] = __fmul_rn(s[j], scale);
                if (diag && (tx * 8 + j > ty * 8 + i)) s[j] = -INFINITY;
            }
            float tmax = s[0];
            #pragma unroll
            for (int j = 1; j < 8; j++) tmax = fmaxf(tmax, s[j]);
            #pragma unroll
            for (int o = 1; o < 16; o <<= 1)
                tmax = fmaxf(tmax, __shfl_xor_sync(0xffffffffu, tmax, o, 16));
            float mnew = fmaxf(mrun[i], tmax);
            float alpha = expf(mrun[i] - mnew);
            float p[8], lsum = 0.f;
            #pragma unroll
            for (int j = 0; j < 8; j++) { p[j] = expf(s[j] - mnew); lsum += p[j]; }
            #pragma unroll
            for (int o = 1; o < 16; o <<= 1)
                lsum += __shfl_xor_sync(0xffffffffu, lsum, o, 16);
            lrun[i] = lrun[i] * alpha + lsum;
            mrun[i] = mnew;
            unsigned long long al2 = pk2(alpha, alpha);
            #pragma unroll
            for (int jp = 0; jp < 4; jp++) oacc[i][jp] = mul2_(oacc[i][jp], al2);
            float4 p0 = make_float4(p[0], p[1], p[2], p[3]);
            float4 p1 = make_float4(p[4], p[5], p[6], p[7]);
            int prow = ty * 8 + i;
            *(float4*)(ps + SWZ(prow, tx * 2))     = p0;
            *(float4*)(ps + SWZ(prow, tx * 2 + 1)) = p1;
        }
        __syncthreads();   // P visible; score reads of ks done

        // load V tile over ks
        #pragma unroll 4
        for (int p = 0; p < 16; p++) {
            int r = p * 8 + warp;
            float4 v = *(const float4*)(V + (size_t)(k0 + r) * KVDIM + kvh * HD + lane5 * 4);
            *(float4*)(ks + SWZ(r, lane5)) = v;
        }
        __syncthreads();

        // ---- PV: O[ty*8+i][tx*8+..] += P[.][j] * V[j][..], j-order 0..127 ----
        for (int jc = 0; jc < 32; jc++) {
            float4 pv[8];
            #pragma unroll
            for (int i = 0; i < 8; i++) pv[i] = *(const float4*)(ps + SWZ(ty * 8 + i, jc));
            ulonglong2 v0[4], v1[4];
            #pragma unroll
            for (int c = 0; c < 4; c++) {
                v0[c] = *(const ulonglong2*)(ks + SWZ(jc * 4 + c, tx * 2));
                v1[c] = *(const ulonglong2*)(ks + SWZ(jc * 4 + c, tx * 2 + 1));
            }
            #pragma unroll
            for (int c = 0; c < 4; c++) {
                #pragma unroll
                for (int i = 0; i < 8; i++) {
                    float av = ((const float*)&pv[i])[c];
                    unsigned long long a2 = pk2(av, av);
                    oacc[i][0] = fma2_(a2, v0[c].x, oacc[i][0]);
                    oacc[i][1] = fma2_(a2, v0[c].y, oacc[i][1]);
                    oacc[i][2] = fma2_(a2, v1[c].x, oacc[i][2]);
                    oacc[i][3] = fma2_(a2, v1[c].y, oacc[i][3]);
                }
            }
        }
    }

    // ---- epilogue ----
    #pragma unroll
    for (int i = 0; i < 8; i++) {
        float inv = __fdiv_rn(1.f, lrun[i]);
        float o[8];
        #pragma unroll
        for (int jp = 0; jp < 4; jp++) upk2(oacc[i][jp], o[2 * jp], o[2 * jp + 1]);
        #pragma unroll
        for (int c = 0; c < 8; c++) o[c] = __fmul_rn(o[c], inv);
        float* op = O + (size_t)(q0 + ty * 8 + i) * HDIM + h * HD + tx * 8;
        *(float4*)(op)     = make_float4(o[0], o[1], o[2], o[3]);
        *(float4*)(op + 4) = make_float4(o[4], o[5], o[6], o[7]);
    }
}

// ---------------- launch ---------------------------------------------------
extern "C" void kernel_launch(void* const* d_in, const int* in_sizes, int n_in,
                              void* d_out, int out_size) {
    const float* hidden = (const float*)d_in[0];
    const float* cosb   = (const float*)d_in[1];
    const float* sinb   = (const float*)d_in[2];
    const float* Wq     = (const float*)d_in[3];
    const float* Wk     = (const float*)d_in[4];
    const float* Wv     = (const float*)d_in[5];
    const float* Wo     = (const float*)d_in[6];
    float* out = (float*)d_out;

    void *px, *psx, *pwq, *pswq, *pwk, *pswk, *pwv, *pswv, *pwo, *pswo;
    void *pq, *pk, *pv, *pattn, *pattn8, *psattn;
    cudaGetSymbolAddress(&px, i8_x);      cudaGetSymbolAddress(&psx, s_x);
    cudaGetSymbolAddress(&pwq, i8_wq);    cudaGetSymbolAddress(&pswq, s_wq);
    cudaGetSymbolAddress(&pwk, i8_wk);    cudaGetSymbolAddress(&pswk, s_wk);
    cudaGetSymbolAddress(&pwv, i8_wv);    cudaGetSymbolAddress(&pswv, s_wv);
    cudaGetSymbolAddress(&pwo, i8_wo);    cudaGetSymbolAddress(&pswo, s_wo);
    cudaGetSymbolAddress(&pq, g_q);       cudaGetSymbolAddress(&pk, g_k);
    cudaGetSymbolAddress(&pv, g_v);       cudaGetSymbolAddress(&pattn, g_attn);
    cudaGetSymbolAddress(&pattn8, i8_attn); cudaGetSymbolAddress(&psattn, s_attn);

    int8_t* x8 = (int8_t*)px;    float* sx = (float*)psx;
    int8_t* wq8 = (int8_t*)pwq;  float* swq = (float*)pswq;
    int8_t* wk8 = (int8_t*)pwk;  float* swk = (float*)pswk;
    int8_t* wv8 = (int8_t*)pwv;  float* swv = (float*)pswv;
    int8_t* wo8 = (int8_t*)pwo;  float* swo = (float*)pswo;
    float* q = (float*)pq;  float* k = (float*)pk;  float* v = (float*)pv;
    float* attn = (float*)pattn;
    int8_t* attn8 = (int8_t*)pattn8; float* sattn = (float*)psattn;

    // 1. fake-quant -> int8 + scales
    rowquant_kernel<<<SEQ, 256>>>(hidden, x8, sx, HDIM);
    rowquant_kernel<<<HDIM, 256>>>(Wq, wq8, swq, HDIM);
    rowquant_kernel<<<KVDIM, 256>>>(Wk, wk8, swk, HDIM);
    rowquant_kernel<<<KVDIM, 256>>>(Wv, wv8, swv, HDIM);
    rowquant_kernel<<<HDIM, 256>>>(Wo, wo8, swo, HDIM);

    // 2. projections (exact int8 tensor cores + fp32 scaling)
    gemm_s8_kernel<<<dim3(HDIM / BN, SEQ / BM), 256>>>(x8, wq8, sx, swq, q, SEQ, HDIM, HDIM);
    gemm_s8_kernel<<<dim3(KVDIM / BN, SEQ / BM), 256>>>(x8, wk8, sx, swk, k, SEQ, KVDIM, HDIM);
    gemm_s8_kernel<<<dim3(KVDIM / BN, SEQ / BM), 256>>>(x8, wv8, sx, swv, v, SEQ, KVDIM, HDIM);

    // 3. RoPE
    rope_kernel<<<dim3(SEQ, NH), 64>>>(q, cosb, sinb, NH);
    rope_kernel<<<dim3(SEQ, NKV), 64>>>(k, cosb, sinb, NKV);

    // 4. attention (128x128 tiles, f32x2, register softmax)
    cudaFuncSetAttribute(attn_kernel, cudaFuncAttributeMaxDynamicSharedMemorySize, ATTN_SMEM);
    attn_kernel<<<dim3(SEQ / 128, NH), 256, ATTN_SMEM>>>(q, k, v, attn);

    // 5. output quant + projection
    rowquant_kernel<<<SEQ, 256>>>(attn, attn8, sattn, HDIM);
    gemm_s8_kernel<<<dim3(HDIM / BN, SEQ / BM), 256>>>(attn8, wo8, sattn, swo, out, SEQ, HDIM, HDIM);
}

// round 6
// speedup vs baseline: 8.3427x; 1.0744x over previous
#include <cuda_runtime.h>
#include <math.h>
#include <stdint.h>

#define SEQ 2048
#define HDIM 4096
#define NH 32
#define NKV 8
#define HD 128
#define GROUPS 4
#define KVDIM (NKV*HD)   // 1024

// ---------------- scratch (static device memory) ---------------------------
__device__ int8_t i8_x[SEQ*HDIM];     __device__ float s_x[SEQ];
__device__ int8_t i8_wq[HDIM*HDIM];   __device__ float s_wq[HDIM];
__device__ int8_t i8_wk[KVDIM*HDIM];  __device__ float s_wk[KVDIM];
__device__ int8_t i8_wv[KVDIM*HDIM];  __device__ float s_wv[KVDIM];
__device__ int8_t i8_wo[HDIM*HDIM];   __device__ float s_wo[HDIM];
__device__ int8_t i8_attn[SEQ*HDIM];  __device__ float s_attn[SEQ];
__device__ float g_q[SEQ*NH*HD];
__device__ float g_k[SEQ*KVDIM];
__device__ float g_v[SEQ*KVDIM];
__device__ float g_attn[SEQ*HDIM];

// ---------------- packed f32x2 helpers (exact per-lane fp32 FMA) -----------
__device__ __forceinline__ unsigned long long pk2(float x, float y) {
    unsigned long long r; asm("mov.b64 %0, {%1, %2};" : "=l"(r) : "f"(x), "f"(y)); return r;
}
__device__ __forceinline__ void upk2(unsigned long long v, float& x, float& y) {
    asm("mov.b64 {%0, %1}, %2;" : "=f"(x), "=f"(y) : "l"(v));
}
__device__ __forceinline__ unsigned long long fma2_(unsigned long long a,
                                                    unsigned long long b,
                                                    unsigned long long c) {
    unsigned long long d;
    asm("fma.rn.f32x2 %0, %1, %2, %3;" : "=l"(d) : "l"(a), "l"(b), "l"(c));
    return d;
}
__device__ __forceinline__ unsigned long long mul2_(unsigned long long a,
                                                    unsigned long long b) {
    unsigned long long d;
    asm("mul.rn.f32x2 %0, %1, %2;" : "=l"(d) : "l"(a), "l"(b));
    return d;
}

// ---------------- cp.async helpers -----------------------------------------
__device__ __forceinline__ void cpa16(void* dst, const void* src) {
    unsigned d = (unsigned)__cvta_generic_to_shared(dst);
    asm volatile("cp.async.cg.shared.global [%0], [%1], 16;\n" :: "r"(d), "l"(src));
}
__device__ __forceinline__ void cpa_commit() {
    asm volatile("cp.async.commit_group;\n");
}
template<int N> __device__ __forceinline__ void cpa_wait() {
    asm volatile("cp.async.wait_group %0;\n" :: "n"(N));
}

// ---------------- row-wise fake quant -> int8 + scale (L=4096) -------------
__global__ void rowquant_kernel(const float* __restrict__ in,
                                int8_t* __restrict__ out8,
                                float* __restrict__ scales) {
    int row = blockIdx.x;
    const float4* x = (const float4*)(in + (size_t)row * 4096);
    char4* y = (char4*)(out8 + (size_t)row * 4096);
    float4 v[4];
    float m = 0.f;
    #pragma unroll
    for (int p = 0; p < 4; p++) {
        v[p] = x[p * 256 + threadIdx.x];
        m = fmaxf(m, fmaxf(fmaxf(fabsf(v[p].x), fabsf(v[p].y)),
                           fmaxf(fabsf(v[p].z), fabsf(v[p].w))));
    }
    __shared__ float red[256];
    red[threadIdx.x] = m;
    __syncthreads();
    for (int s = 128; s > 0; s >>= 1) {
        if (threadIdx.x < s) red[threadIdx.x] = fmaxf(red[threadIdx.x], red[threadIdx.x + s]);
        __syncthreads();
    }
    float scale = fmaxf(__fdiv_rn(red[0], 127.0f), 1e-8f);
    if (threadIdx.x == 0) scales[row] = scale;
    #pragma unroll
    for (int p = 0; p < 4; p++) {
        float q0 = fminf(fmaxf(rintf(__fdiv_rn(v[p].x, scale)), -128.f), 127.f);
        float q1 = fminf(fmaxf(rintf(__fdiv_rn(v[p].y, scale)), -128.f), 127.f);
        float q2 = fminf(fmaxf(rintf(__fdiv_rn(v[p].z, scale)), -128.f), 127.f);
        float q3 = fminf(fmaxf(rintf(__fdiv_rn(v[p].w, scale)), -128.f), 127.f);
        y[p * 256 + threadIdx.x] = make_char4((int8_t)(int)q0, (int8_t)(int)q1,
                                              (int8_t)(int)q2, (int8_t)(int)q3);
    }
}

// ---------------- int8 IMMA GEMM body, cp.async double-buffered, K=4096 ----
#define BM 128
#define BN 128
#define BKQ 64
#define ASTRB 80
#define NKSTEPS (HDIM / BKQ)   // 64

struct GemmSmem {
    uint8_t As[2][BM * ASTRB];
    uint8_t Bs[2][BN * ASTRB];
};

__device__ __forceinline__ void gemm_body(
    const int8_t* __restrict__ A, const int8_t* __restrict__ B,
    const float* __restrict__ sa, const float* __restrict__ sb,
    float* __restrict__ C, int Nst, int m0, int n0, GemmSmem& sh) {
    int tid = threadIdx.x;
    int warp = tid >> 5, lane = tid & 31;
    int gid = lane >> 2, tig = lane & 3;
    int wm0 = (warp & 1) * 64;
    int wn0 = (warp >> 1) * 32;
    int lrow = tid >> 2;
    int lcol = (tid & 3) * 16;

    int acc[4][4][4];
    #pragma unroll
    for (int i = 0; i < 4; i++)
        #pragma unroll
        for (int j = 0; j < 4; j++)
            #pragma unroll
            for (int c = 0; c < 4; c++) acc[i][j][c] = 0;

    // prologue: load buffer 0
    #pragma unroll
    for (int p = 0; p < 2; p++) {
        int r = lrow + p * 64;
        cpa16(sh.As[0] + r * ASTRB + lcol, A + (size_t)(m0 + r) * HDIM + lcol);
        cpa16(sh.Bs[0] + r * ASTRB + lcol, B + (size_t)(n0 + r) * HDIM + lcol);
    }
    cpa_commit();

    for (int it = 0; it < NKSTEPS; it++) {
        if (it + 1 < NKSTEPS) {
            int nb = (it + 1) & 1;
            int k0 = (it + 1) * BKQ;
            #pragma unroll
            for (int p = 0; p < 2; p++) {
                int r = lrow + p * 64;
                cpa16(sh.As[nb] + r * ASTRB + lcol, A + (size_t)(m0 + r) * HDIM + k0 + lcol);
                cpa16(sh.Bs[nb] + r * ASTRB + lcol, B + (size_t)(n0 + r) * HDIM + k0 + lcol);
            }
            cpa_commit();
            cpa_wait<1>();
        } else {
            cpa_wait<0>();
        }
        __syncthreads();
        const uint32_t* As32 = (const uint32_t*)sh.As[it & 1];
        const uint32_t* Bs32 = (const uint32_t*)sh.Bs[it & 1];
        #pragma unroll
        for (int ks = 0; ks < 2; ks++) {
            int kb = ks * 8;
            uint32_t a[4][4], b[4][2];
            #pragma unroll
            for (int mi = 0; mi < 4; mi++) {
                int r1 = wm0 + mi * 16 + gid;
                a[mi][0] = As32[r1 * 20 + kb + tig];
                a[mi][1] = As32[(r1 + 8) * 20 + kb + tig];
                a[mi][2] = As32[r1 * 20 + kb + tig + 4];
                a[mi][3] = As32[(r1 + 8) * 20 + kb + tig + 4];
            }
            #pragma unroll
            for (int ni = 0; ni < 4; ni++) {
                int rb = wn0 + ni * 8 + gid;
                b[ni][0] = Bs32[rb * 20 + kb + tig];
                b[ni][1] = Bs32[rb * 20 + kb + tig + 4];
            }
            #pragma unroll
            for (int mi = 0; mi < 4; mi++)
                #pragma unroll
                for (int ni = 0; ni < 4; ni++) {
                    asm volatile(
                        "mma.sync.aligned.m16n8k32.row.col.s32.s8.s8.s32 "
                        "{%0,%1,%2,%3}, {%4,%5,%6,%7}, {%8,%9}, {%0,%1,%2,%3};\n"
                        : "+r"(acc[mi][ni][0]), "+r"(acc[mi][ni][1]),
                          "+r"(acc[mi][ni][2]), "+r"(acc[mi][ni][3])
                        : "r"(a[mi][0]), "r"(a[mi][1]), "r"(a[mi][2]), "r"(a[mi][3]),
                          "r"(b[ni][0]), "r"(b[ni][1]));
                }
        }
        __syncthreads();
    }
    #pragma unroll
    for (int mi = 0; mi < 4; mi++) {
        int r0 = m0 + wm0 + mi * 16 + gid;
        float sa0 = sa[r0], sa1 = sa[r0 + 8];
        #pragma unroll
        for (int ni = 0; ni < 4; ni++) {
            int c = n0 + wn0 + ni * 8 + tig * 2;
            float sb0 = sb[c - n0 + n0], sb1 = sb[c + 1 - n0 + n0];
            *(float2*)(C + (size_t)r0 * Nst + c) = make_float2(
                __fmul_rn(__fmul_rn((float)acc[mi][ni][0], sa0), sb0),
                __fmul_rn(__fmul_rn((float)acc[mi][ni][1], sa0), sb1));
            *(float2*)(C + (size_t)(r0 + 8) * Nst + c) = make_float2(
                __fmul_rn(__fmul_rn((float)acc[mi][ni][2], sa1), sb0),
                __fmul_rn(__fmul_rn((float)acc[mi][ni][3], sa1), sb1));
        }
    }
}

// fused QKV: grid.x = 48 (32 Q blocks, 8 K, 8 V), grid.y = SEQ/128
__global__ void __launch_bounds__(256, 2)
gemm_qkv_kernel(const int8_t* __restrict__ x8, const float* __restrict__ sx) {
    __shared__ GemmSmem sh;
    int bx = blockIdx.x;
    int m0 = blockIdx.y * BM;
    if (bx < 32) {
        gemm_body(x8, i8_wq, sx, s_wq, g_q, HDIM, m0, bx * BN, sh);
    } else if (bx < 40) {
        gemm_body(x8, i8_wk, sx, s_wk, g_k, KVDIM, m0, (bx - 32) * BN, sh);
    } else {
        gemm_body(x8, i8_wv, sx, s_wv, g_v, KVDIM, m0, (bx - 40) * BN, sh);
    }
}

// generic single GEMM (output projection)
__global__ void __launch_bounds__(256, 2)
gemm_s8_kernel(const int8_t* __restrict__ A, const int8_t* __restrict__ B,
               const float* __restrict__ sa, const float* __restrict__ sb,
               float* __restrict__ C, int Nst) {
    __shared__ GemmSmem sh;
    gemm_body(A, B, sa, sb, C, Nst, blockIdx.y * BM, blockIdx.x * BN, sh);
}

// ---------------- RoPE (in-place) ------------------------------------------
__global__ void rope_kernel(float* __restrict__ q, const float* __restrict__ cosb,
                            const float* __restrict__ sinb, int nheads) {
    int s = blockIdx.x;
    int h = blockIdx.y;
    int d = threadIdx.x;
    float* row = q + (size_t)s * nheads * HD + h * HD;
    float c1 = cosb[s * HD + d],      s1 = sinb[s * HD + d];
    float c2 = cosb[s * HD + d + 64], s2 = sinb[s * HD + d + 64];
    float x1 = row[d], x2 = row[d + 64];
    row[d]      = __fsub_rn(__fmul_rn(x1, c1), __fmul_rn(x2, s1));
    row[d + 64] = __fadd_rn(__fmul_rn(x2, c2), __fmul_rn(x1, s2));
}

// ---------------- causal GQA flash attention, 128x128 tiles, f32x2 ---------
#define SWZ(row, c4) (((row) << 9) + (((c4) << 4) ^ ((((row) >> 3) & 7) << 4)))
#define ATTN_SMEM (3 * 128 * 512)

__global__ void __launch_bounds__(256, 1)
attn_kernel(const float* __restrict__ Q, const float* __restrict__ K,
            const float* __restrict__ V, float* __restrict__ O) {
    extern __shared__ char smem[];
    char* qs = smem;                 // Q tile  [128][128]f
    char* ks = smem + 65536;         // K tile, reused for V
    char* ps = smem + 131072;        // P tile  [128][128]f
    int h = blockIdx.y;
    int kvh = h / GROUPS;
    int qi = (int)gridDim.x - 1 - (int)blockIdx.x;   // heavy tiles first
    int q0 = qi * 128;
    int t = threadIdx.x;
    int lane5 = t & 31, warp = t >> 5;
    int tx = t & 15, ty = t >> 4;
    const float scale = 0.08838834764831845f;

    #pragma unroll 4
    for (int p = 0; p < 16; p++) {
        int r = p * 8 + warp;
        float4 v = *(const float4*)(Q + (size_t)(q0 + r) * (NH * HD) + h * HD + lane5 * 4);
        *(float4*)(qs + SWZ(r, lane5)) = v;
    }

    unsigned long long oacc[8][4];
    float mrun[8], lrun[8];
    #pragma unroll
    for (int i = 0; i < 8; i++) {
        mrun[i] = -INFINITY; lrun[i] = 0.f;
        #pragma unroll
        for (int jp = 0; jp < 4; jp++) oacc[i][jp] = 0ull;
    }

    for (int kt = 0; kt <= qi; kt++) {
        int k0 = kt * 128;
        __syncthreads();
        #pragma unroll 4
        for (int p = 0; p < 16; p++) {
            int r = p * 8 + warp;
            float4 v = *(const float4*)(K + (size_t)(k0 + r) * KVDIM + kvh * HD + lane5 * 4);
            *(float4*)(ks + SWZ(r, lane5)) = v;
        }
        __syncthreads();

        unsigned long long sacc[8][4];
        #pragma unroll
        for (int i = 0; i < 8; i++)
            #pragma unroll
            for (int jp = 0; jp < 4; jp++) sacc[i][jp] = 0ull;

        for (int dc = 0; dc < 32; dc++) {
            float4 qv[8], kv[8];
            #pragma unroll
            for (int i = 0; i < 8; i++) qv[i] = *(const float4*)(qs + SWZ(ty * 8 + i, dc));
            #pragma unroll
            for (int j = 0; j < 8; j++) kv[j] = *(const float4*)(ks + SWZ(tx * 8 + j, dc));
            #pragma unroll
            for (int c = 0; c < 4; c++) {
                unsigned long long b2[4];
                #pragma unroll
                for (int jp = 0; jp < 4; jp++) {
                    float b0 = ((const float*)&kv[2 * jp])[c];
                    float b1 = ((const float*)&kv[2 * jp + 1])[c];
                    b2[jp] = pk2(b0, b1);
                }
                #pragma unroll
                for (int i = 0; i < 8; i++) {
                    float av = ((const float*)&qv[i])[c];
                    unsigned long long a2 = pk2(av, av);
                    #pragma unroll
                    for (int jp = 0; jp < 4; jp++)
                        sacc[i][jp] = fma2_(a2, b2[jp], sacc[i][jp]);
                }
            }
        }

        bool diag = (kt == qi);
        #pragma unroll
        for (int i = 0; i < 8; i++) {
            float s[8];
            #pragma unroll
            for (int jp = 0; jp < 4; jp++) upk2(sacc[i][jp], s[2 * jp], s[2 * jp + 1]);
            #pragma unroll
            for (int j = 0; j < 8; j++) {
                s[j] = __fmul_rn(s[j], scale);
                if (diag && (tx * 8 + j > ty * 8 + i)) s[j] = -INFINITY;
            }
            float tmax = s[0];
            #pragma unroll
            for (int j = 1; j < 8; j++) tmax = fmaxf(tmax, s[j]);
            #pragma unroll
            for (int o = 1; o < 16; o <<= 1)
                tmax = fmaxf(tmax, __shfl_xor_sync(0xffffffffu, tmax, o, 16));
            float mnew = fmaxf(mrun[i], tmax);
            float alpha = expf(mrun[i] - mnew);
            float p[8], lsum = 0.f;
            #pragma unroll
            for (int j = 0; j < 8; j++) { p[j] = expf(s[j] - mnew); lsum += p[j]; }
            #pragma unroll
            for (int o = 1; o < 16; o <<= 1)
                lsum += __shfl_xor_sync(0xffffffffu, lsum, o, 16);
            lrun[i] = lrun[i] * alpha + lsum;
            mrun[i] = mnew;
            unsigned long long al2 = pk2(alpha, alpha);
            #pragma unroll
            for (int jp = 0; jp < 4; jp++) oacc[i][jp] = mul2_(oacc[i][jp], al2);
            float4 p0 = make_float4(p[0], p[1], p[2], p[3]);
            float4 p1 = make_float4(p[4], p[5], p[6], p[7]);
            int prow = ty * 8 + i;
            *(float4*)(ps + SWZ(prow, tx * 2))     = p0;
            *(float4*)(ps + SWZ(prow, tx * 2 + 1)) = p1;
        }
        __syncthreads();

        #pragma unroll 4
        for (int p = 0; p < 16; p++) {
            int r = p * 8 + warp;
            float4 v = *(const float4*)(V + (size_t)(k0 + r) * KVDIM + kvh * HD + lane5 * 4);
            *(float4*)(ks + SWZ(r, lane5)) = v;
        }
        __syncthreads();

        for (int jc = 0; jc < 32; jc++) {
            float4 pv[8];
            #pragma unroll
            for (int i = 0; i < 8; i++) pv[i] = *(const float4*)(ps + SWZ(ty * 8 + i, jc));
            ulonglong2 v0[4], v1[4];
            #pragma unroll
            for (int c = 0; c < 4; c++) {
                v0[c] = *(const ulonglong2*)(ks + SWZ(jc * 4 + c, tx * 2));
                v1[c] = *(const ulonglong2*)(ks + SWZ(jc * 4 + c, tx * 2 + 1));
            }
            #pragma unroll
            for (int c = 0; c < 4; c++) {
                #pragma unroll
                for (int i = 0; i < 8; i++) {
                    float av = ((const float*)&pv[i])[c];
                    unsigned long long a2 = pk2(av, av);
                    oacc[i][0] = fma2_(a2, v0[c].x, oacc[i][0]);
                    oacc[i][1] = fma2_(a2, v0[c].y, oacc[i][1]);
                    oacc[i][2] = fma2_(a2, v1[c].x, oacc[i][2]);
                    oacc[i][3] = fma2_(a2, v1[c].y, oacc[i][3]);
                }
            }
        }
    }

    #pragma unroll
    for (int i = 0; i < 8; i++) {
        float inv = __fdiv_rn(1.f, lrun[i]);
        float o[8];
        #pragma unroll
        for (int jp = 0; jp < 4; jp++) upk2(oacc[i][jp], o[2 * jp], o[2 * jp + 1]);
        #pragma unroll
        for (int c = 0; c < 8; c++) o[c] = __fmul_rn(o[c], inv);
        float* op = O + (size_t)(q0 + ty * 8 + i) * HDIM + h * HD + tx * 8;
        *(float4*)(op)     = make_float4(o[0], o[1], o[2], o[3]);
        *(float4*)(op + 4) = make_float4(o[4], o[5], o[6], o[7]);
    }
}

// ---------------- launch ---------------------------------------------------
extern "C" void kernel_launch(void* const* d_in, const int* in_sizes, int n_in,
                              void* d_out, int out_size) {
    const float* hidden = (const float*)d_in[0];
    const float* cosb   = (const float*)d_in[1];
    const float* sinb   = (const float*)d_in[2];
    const float* Wq     = (const float*)d_in[3];
    const float* Wk     = (const float*)d_in[4];
    const float* Wv     = (const float*)d_in[5];
    const float* Wo     = (const float*)d_in[6];
    float* out = (float*)d_out;

    void *px, *psx, *pwq, *pswq, *pwk, *pswk, *pwv, *pswv, *pwo, *pswo;
    void *pq, *pk, *pv, *pattn, *pattn8, *psattn;
    cudaGetSymbolAddress(&px, i8_x);      cudaGetSymbolAddress(&psx, s_x);
    cudaGetSymbolAddress(&pwq, i8_wq);    cudaGetSymbolAddress(&pswq, s_wq);
    cudaGetSymbolAddress(&pwk, i8_wk);    cudaGetSymbolAddress(&pswk, s_wk);
    cudaGetSymbolAddress(&pwv, i8_wv);    cudaGetSymbolAddress(&pswv, s_wv);
    cudaGetSymbolAddress(&pwo, i8_wo);    cudaGetSymbolAddress(&pswo, s_wo);
    cudaGetSymbolAddress(&pq, g_q);       cudaGetSymbolAddress(&pk, g_k);
    cudaGetSymbolAddress(&pv, g_v);       cudaGetSymbolAddress(&pattn, g_attn);
    cudaGetSymbolAddress(&pattn8, i8_attn); cudaGetSymbolAddress(&psattn, s_attn);

    int8_t* x8 = (int8_t*)px;    float* sx = (float*)psx;
    int8_t* wq8 = (int8_t*)pwq;  float* swq = (float*)pswq;
    int8_t* wk8 = (int8_t*)pwk;  float* swk = (float*)pswk;
    int8_t* wv8 = (int8_t*)pwv;  float* swv = (float*)pswv;
    int8_t* wo8 = (int8_t*)pwo;  float* swo = (float*)pswo;
    float* q = (float*)pq;  float* k = (float*)pk;  float* v = (float*)pv;
    float* attn = (float*)pattn;
    int8_t* attn8 = (int8_t*)pattn8; float* sattn = (float*)psattn;

    // 1. fake-quant -> int8 + scales (all rows are length 4096)
    rowquant_kernel<<<SEQ, 256>>>(hidden, x8, sx);
    rowquant_kernel<<<HDIM, 256>>>(Wq, wq8, swq);
    rowquant_kernel<<<KVDIM, 256>>>(Wk, wk8, swk);
    rowquant_kernel<<<KVDIM, 256>>>(Wv, wv8, swv);
    rowquant_kernel<<<HDIM, 256>>>(Wo, wo8, swo);

    // 2. fused QKV projections (int8 tensor cores, cp.async pipelined)
    gemm_qkv_kernel<<<dim3(48, SEQ / BM), 256>>>(x8, sx);

    // 3. RoPE
    rope_kernel<<<dim3(SEQ, NH), 64>>>(q, cosb, sinb, NH);
    rope_kernel<<<dim3(SEQ, NKV), 64>>>(k, cosb, sinb, NKV);

    // 4. attention (128x128 tiles, f32x2, register softmax)
    cudaFuncSetAttribute(attn_kernel, cudaFuncAttributeMaxDynamicSharedMemorySize, ATTN_SMEM);
    attn_kernel<<<dim3(SEQ / 128, NH), 256, ATTN_SMEM>>>(q, k, v, attn);

    // 5. output quant + projection
    rowquant_kernel<<<SEQ, 256>>>(attn, attn8, sattn);
    gemm_s8_kernel<<<dim3(HDIM / BN, SEQ / BM), 256>>>(attn8, wo8, sattn, swo, out, HDIM);
}